// round 8
// baseline (speedup 1.0000x reference)
#include <cuda_runtime.h>
#include <cuda_fp16.h>
#include <cstdint>

#define NN   8192
#define FIN  256
#define FOUT 128
#define L2E  1.44269504f
#define LRA  0.2f
#define CK   128                   // j per chunk
#define JSPLIT 4
#define JBLK (NN / JSPLIT)         // 2048
#define NCH  (JBLK / CK)           // 16 chunks per block
#define RBLK 256                   // rows per block
#define NTI  (NN / 64)             // 128 prebuilt 64j B tiles
#define TB64 16384                 // one 64j tile: 64j x 128d x 2B
#define TILE_BYTES 32768           // per-chunk buffer: 2 x 64j tiles

__device__ __align__(16)  float g_h[NN * FOUT];
__device__ float g_e1s[NN];        // 1.4427 * e1
__device__ float g_e2s[NN];        // 1.4427 * e2
__device__ __align__(128) unsigned char g_bt[(size_t)NTI * TB64];        // 2MB
__device__ uint4 g_ab[NN / CK][NN];                                      // adj bitmask, 8MB
__device__ __align__(16)  float g_part[JSPLIT][NN * FOUT];               // 16MB
__device__ float g_psum[JSPLIT][NN];

// ------------------------- helpers -----------------------------------------
__device__ __forceinline__ uint32_t smem_u32(const void* p) {
    uint32_t a;
    asm("{ .reg .u64 t; cvta.to.shared.u64 t, %1; cvt.u32.u64 %0, t; }" : "=r"(a) : "l"(p));
    return a;
}
__device__ __forceinline__ uint32_t pack16(float lo, float hi) {
    uint32_t r;  // low 16 bits = lo (lower k index)
    asm("cvt.rn.f16x2.f32 %0, %1, %2;" : "=r"(r) : "f"(hi), "f"(lo));
    return r;
}
// pack two probs and mask them with adjacency bits (w >> sh) & 1, (w >> sh+1) & 1
__device__ __forceinline__ uint32_t packm2(float lo, float hi, uint32_t w, int sh) {
    uint32_t p = pack16(lo, hi);
    uint32_t m = ((w >> sh) & 1u) * 0x3C00u + ((w >> (sh + 1)) & 1u) * 0x3C000000u;
    uint32_t r;
    asm("mul.f16x2 %0, %1, %2;" : "=r"(r) : "r"(p), "r"(m));
    return r;
}
__device__ __forceinline__ float pcalc(float se1, float se2) {
    float s = se1 + se2;
    s = fmaxf(s, LRA * s);          // lrelu commutes with positive scale
    float p;
    asm("ex2.approx.f32 %0, %1;" : "=f"(p) : "f"(s));
    return p;
}
__device__ __forceinline__ void mma16816(float* c, const uint32_t* a, const uint32_t* b) {
    asm volatile("mma.sync.aligned.m16n8k16.row.col.f32.f16.f16.f32 "
        "{%0,%1,%2,%3}, {%4,%5,%6,%7}, {%8,%9}, {%0,%1,%2,%3};"
        : "+f"(c[0]), "+f"(c[1]), "+f"(c[2]), "+f"(c[3])
        : "r"(a[0]), "r"(a[1]), "r"(a[2]), "r"(a[3]), "r"(b[0]), "r"(b[1]));
}
#define LDMX4(r, a) \
    asm volatile("ldmatrix.sync.aligned.m8n8.x4.shared.b16 {%0,%1,%2,%3}, [%4];" \
        : "=r"((r)[0]), "=r"((r)[1]), "=r"((r)[2]), "=r"((r)[3]) : "r"(a))
#define CP_ASYNC(dst, src) \
    asm volatile("cp.async.cg.shared.global [%0], [%1], 16;" :: "r"(dst), "l"(src))
#define CP_COMMIT() asm volatile("cp.async.commit_group;" ::: "memory")
#define CP_WAIT1()  asm volatile("cp.async.wait_group 1;"  ::: "memory")

// ---------------------------------------------------------------------------
// Kernel 0 (bits): compress adj int32 -> bitmask. Warp per row, 64 chunks of
// 128 j; 4 coalesced 128B loads + 4 ballots per chunk. Pure DRAM stream.
// ---------------------------------------------------------------------------
__global__ __launch_bounds__(256) void k_bits(const int* __restrict__ adj)
{
    const int w = (blockIdx.x << 3) + (threadIdx.x >> 5);   // row, 8192 warps
    const int l = threadIdx.x & 31;
    const int* rp = adj + (size_t)w * NN;
    for (int c = 0; c < NN / CK; c++) {
        const int jb = c * CK;
        uint32_t b0 = __ballot_sync(0xFFFFFFFFu, rp[jb + l]        != 0);
        uint32_t b1 = __ballot_sync(0xFFFFFFFFu, rp[jb + 32 + l]   != 0);
        uint32_t b2 = __ballot_sync(0xFFFFFFFFu, rp[jb + 64 + l]   != 0);
        uint32_t b3 = __ballot_sync(0xFFFFFFFFu, rp[jb + 96 + l]   != 0);
        if (l == 0) g_ab[c][w] = make_uint4(b0, b1, b2, b3);
    }
}

// ---------------------------------------------------------------------------
// Kernel 1: h = x @ trans  (32-row tiles, 256 CTAs)
// ---------------------------------------------------------------------------
__global__ __launch_bounds__(256) void k_gemm_h(const float* __restrict__ x,
                                                const float* __restrict__ trans)
{
    __shared__ float xs[32 * 32];
    __shared__ float ts[32 * FOUT];
    const int t = threadIdx.x;
    const int rowbase = blockIdx.x * 32;
    const int ty = t >> 5;
    const int tx = t & 31;

    float acc[4][4];
    #pragma unroll
    for (int i = 0; i < 4; i++)
        #pragma unroll
        for (int c = 0; c < 4; c++) acc[i][c] = 0.f;

    const float4* x4 = (const float4*)x;
    const float4* t4 = (const float4*)trans;

    for (int k0 = 0; k0 < FIN; k0 += 32) {
        {
            int r = t >> 3, c = t & 7;
            ((float4*)xs)[r * 8 + c] = x4[(size_t)(rowbase + r) * (FIN/4) + (k0 >> 2) + c];
        }
        #pragma unroll
        for (int v = t, i = 0; i < 4; i++, v += 256) {
            int r = v >> 5, c = v & 31;
            ((float4*)ts)[r * 32 + c] = t4[(size_t)(k0 + r) * (FOUT/4) + c];
        }
        __syncthreads();
        #pragma unroll
        for (int kk = 0; kk < 32; kk++) {
            float4 b = *(const float4*)&ts[kk * FOUT + tx * 4];
            #pragma unroll
            for (int i = 0; i < 4; i++) {
                float a = xs[(ty * 4 + i) * 32 + kk];
                acc[i][0] += a * b.x; acc[i][1] += a * b.y;
                acc[i][2] += a * b.z; acc[i][3] += a * b.w;
            }
        }
        __syncthreads();
    }
    #pragma unroll
    for (int i = 0; i < 4; i++) {
        float4 o = make_float4(acc[i][0], acc[i][1], acc[i][2], acc[i][3]);
        *(float4*)&g_h[(size_t)(rowbase + ty * 4 + i) * FOUT + tx * 4] = o;
    }
}

// ---------------------------------------------------------------------------
// Kernel 2: e1/e2 (pre-scaled by log2(e))
// ---------------------------------------------------------------------------
__global__ __launch_bounds__(256) void k_e(const float* __restrict__ aw)
{
    const int row  = blockIdx.x * 8 + (threadIdx.x >> 5);
    const int lane = threadIdx.x & 31;
    float s1 = 0.f, s2 = 0.f;
    #pragma unroll
    for (int d = lane; d < FOUT; d += 32) {
        float v = g_h[(size_t)row * FOUT + d];
        s1 += v * aw[d];
        s2 += v * aw[FOUT + d];
    }
    #pragma unroll
    for (int o = 16; o; o >>= 1) {
        s1 += __shfl_xor_sync(0xFFFFFFFFu, s1, o);
        s2 += __shfl_xor_sync(0xFFFFFFFFu, s2, o);
    }
    if (lane == 0) { g_e1s[row] = s1 * L2E; g_e2s[row] = s2 * L2E; }
}

// ---------------------------------------------------------------------------
// Kernel 3 (prep): build B = h^T 64j tiles (fp16), ldmatrix-ready 8x8 blocks.
// blk = ((step*8+dpair)*2+dn)*2+kk; each blk = 128B: 8 rows (dr) x 8 j.
// Element (dr, jc) = h[j0+step*16+kk*8+jc][dp*16+dn*8+dr].
// ---------------------------------------------------------------------------
__global__ __launch_bounds__(256) void k_prep()
{
    const int tc = blockIdx.x;
    const int t  = threadIdx.x;
    const int j0 = tc * 64;
    unsigned char* tb = g_bt + (size_t)tc * TB64;

    #pragma unroll
    for (int i = 0; i < 4; i++) {
        int rho = i * 256 + t;
        int blk = rho >> 3, dr = rho & 7;
        int kk = blk & 1, dn = (blk >> 1) & 1, dp = (blk >> 2) & 7, st = blk >> 5;
        int d  = dp * 16 + dn * 8 + dr;
        int jb = j0 + st * 16 + kk * 8;
        uint32_t h4[4];
        #pragma unroll
        for (int m = 0; m < 4; m++) {
            float a = g_h[(size_t)(jb + 2*m)     * FOUT + d];
            float b = g_h[(size_t)(jb + 2*m + 1) * FOUT + d];
            h4[m] = pack16(a, b);
        }
        *(uint4*)(tb + (uint32_t)blk * 128 + dr * 16) =
            make_uint4(h4[0], h4[1], h4[2], h4[3]);
    }
}

// ---------------------------------------------------------------------------
// Kernel 4 (main): fused masked-exp + fp16 HMMA attention GEMM.
// 512 threads = 16 warps of m16 x n128 (R6 structure), CK=128 chunks.
// adj via bitmask (2 uint4 per lane per chunk); masks built with shifts+IMAD.
// Row sums via ones-column MMA. B double-buffered 32KB via cp.async.
// ---------------------------------------------------------------------------
__global__ __launch_bounds__(512, 1) void k_main()
{
    extern __shared__ unsigned char smem[];
    const uint32_t sb = smem_u32(smem);
    const int t = threadIdx.x, w = t >> 5, l = t & 31;
    const int bx = blockIdx.x, by = blockIdx.y;
    const int g = l >> 2, qh = l & 3, q2 = qh * 2;
    const int rowb = bx * RBLK + w * 16;
    const size_t jbase = (size_t)by * JBLK;

    // prime B double-buffer (2 x 32KB; 512 threads x 4 vec16 per buffer)
    const unsigned char* bt0 = g_bt + (size_t)by * NCH * TILE_BYTES;
    #pragma unroll
    for (int c = 0; c < 2; c++) {
        uint32_t dst = sb + c * TILE_BYTES + t * 16;
        const unsigned char* src = bt0 + (size_t)c * TILE_BYTES + t * 16;
        #pragma unroll
        for (int i = 0; i < 4; i++) CP_ASYNC(dst + i * 8192, src + i * 8192);
        CP_COMMIT();
    }

    const float se1g = g_e1s[rowb + g];
    const float se1h = g_e1s[rowb + g + 8];

    float c_[16][4];
    #pragma unroll
    for (int td = 0; td < 16; td++)
        #pragma unroll
        for (int k = 0; k < 4; k++) c_[td][k] = 0.f;
    float crs[4] = {0.f, 0.f, 0.f, 0.f};
    const uint32_t bones[2] = {0x3C003C00u, 0x3C003C00u};

    for (int c = 0; c < NCH; c++) {
        const int cIdx = by * NCH + c;
        // adjacency bits for this lane's two rows, whole 128-j chunk
        const uint4 bgv = g_ab[cIdx][rowb + g];
        const uint4 bhv = g_ab[cIdx][rowb + g + 8];
        const uint32_t wga[4] = { bgv.x, bgv.y, bgv.z, bgv.w };
        const uint32_t wha[4] = { bhv.x, bhv.y, bhv.z, bhv.w };

        CP_WAIT1();
        __syncthreads();
        const uint32_t bufb = sb + (c & 1) * TILE_BYTES;

        #pragma unroll
        for (int s = 0; s < 8; s++) {
            const size_t joff = jbase + (size_t)c * CK + 16 * s + q2;
            const float2 e2a = *(const float2*)(g_e2s + joff);
            const float2 e2b = *(const float2*)(g_e2s + joff + 8);

            const uint32_t wg = wga[s >> 1];
            const uint32_t wh = wha[s >> 1];
            const int sh = ((s & 1) << 4) + q2;

            float p00 = pcalc(se1g, e2a.x), p01 = pcalc(se1g, e2a.y);
            float p10 = pcalc(se1h, e2a.x), p11 = pcalc(se1h, e2a.y);
            float p08 = pcalc(se1g, e2b.x), p09 = pcalc(se1g, e2b.y);
            float p18 = pcalc(se1h, e2b.x), p19 = pcalc(se1h, e2b.y);

            uint32_t a[4];
            a[0] = packm2(p00, p01, wg, sh);
            a[1] = packm2(p10, p11, wh, sh);
            a[2] = packm2(p08, p09, wg, sh + 8);
            a[3] = packm2(p18, p19, wh, sh + 8);

            #pragma unroll
            for (int dp = 0; dp < 8; dp++) {
                uint32_t bh[4];
                const uint32_t ad = bufb + (s >> 2) * TB64 + ((s & 3) * 8 + dp) * 512
                                  + (l >> 3) * 128 + (l & 7) * 16;
                LDMX4(bh, ad);
                mma16816(c_[2 * dp],     a, bh);
                mma16816(c_[2 * dp + 1], a, bh + 2);
            }
            mma16816(crs, a, bones);   // row-sum column
        }

        __syncthreads();
        if (c + 2 < NCH) {
            uint32_t dst = sb + (c & 1) * TILE_BYTES + t * 16;
            const unsigned char* src = bt0 + (size_t)(c + 2) * TILE_BYTES + t * 16;
            #pragma unroll
            for (int i = 0; i < 4; i++) CP_ASYNC(dst + i * 8192, src + i * 8192);
        }
        CP_COMMIT();
    }

    // row sums (all n cols identical in crs; qh==0 lanes write)
    if (qh == 0) {
        g_psum[by][rowb + g]     = crs[0];
        g_psum[by][rowb + g + 8] = crs[2];
    }

    // store unnormalized partials
    float* pb = g_part[by];
    #pragma unroll
    for (int td = 0; td < 16; td++) {
        const int col = td * 8 + q2;
        *(float2*)(pb + (size_t)(rowb + g) * FOUT + col) =
            make_float2(c_[td][0], c_[td][1]);
        *(float2*)(pb + (size_t)(rowb + g + 8) * FOUT + col) =
            make_float2(c_[td][2], c_[td][3]);
    }
}

// ---------------------------------------------------------------------------
// Kernel 5 (final): combine j-split partials, normalize, ELU.
// ---------------------------------------------------------------------------
__global__ __launch_bounds__(256) void k_final(float* __restrict__ out)
{
    const int idx = blockIdx.x * 256 + threadIdx.x;   // float4 index
    const int r = idx >> 5;
    float4 v = make_float4(0.f, 0.f, 0.f, 0.f);
    #pragma unroll
    for (int p = 0; p < JSPLIT; p++) {
        float4 a = ((const float4*)g_part[p])[idx];
        v.x += a.x; v.y += a.y; v.z += a.z; v.w += a.w;
    }
    const float inv = 1.f / (g_psum[0][r] + g_psum[1][r] + g_psum[2][r] + g_psum[3][r]);
    float o[4] = { v.x * inv, v.y * inv, v.z * inv, v.w * inv };
    #pragma unroll
    for (int i = 0; i < 4; i++) o[i] = o[i] > 0.f ? o[i] : expm1f(o[i]);
    ((float4*)out)[idx] = make_float4(o[0], o[1], o[2], o[3]);
}

// ---------------------------------------------------------------------------
extern "C" void kernel_launch(void* const* d_in, const int* in_sizes, int n_in,
                              void* d_out, int out_size)
{
    const float* x     = (const float*)d_in[0];
    const int*   adj   = (const int*)d_in[1];
    const float* trans = (const float*)d_in[2];
    const float* aw    = (const float*)d_in[3];
    float*       out   = (float*)d_out;

    const int smem_bytes = 2 * TILE_BYTES;   // 64KB
    cudaFuncSetAttribute(k_main, cudaFuncAttributeMaxDynamicSharedMemorySize, smem_bytes);

    k_bits<<<NN / 8, 256>>>(adj);
    k_gemm_h<<<NN / 32, 256>>>(x, trans);
    k_e<<<NN / 8, 256>>>(aw);
    k_prep<<<NTI, 256>>>();
    dim3 gmain(NN / RBLK, JSPLIT);
    k_main<<<gmain, 512, smem_bytes>>>();
    k_final<<<NN * FOUT / (256 * 4), 256>>>(out);
}